// round 10
// baseline (speedup 1.0000x reference)
#include <cuda_runtime.h>
#include <cuda_fp16.h>
#include <cstdint>
#include <math.h>

#define T_  1024
#define H_  2048
#define I_  1408
#define E_  16
#define IS_ 2816
#define TK  4
#define NA  (T_*TK)   // 4096 token-expert assignments

// ---------------- scratch (device globals) ----------------------------------------------
__device__ __half g_XH   [(size_t)T_ * H_];
__device__ __half g_SGUH [(size_t)H_ * (2*IS_)];
__device__ __half g_SDNH [(size_t)IS_ * H_];
__device__ __half g_ACTH [(size_t)NA * I_];
__device__ __half g_SACTH[(size_t)T_ * IS_];
__device__ float  g_ROUT [(size_t)NA * H_];
__device__ float  g_SH   [(size_t)T_ * H_];
__device__ int    g_eid [NA];
__device__ float  g_tw  [NA];
__device__ int    g_cnt [E_];
__device__ int    g_rows[E_ * T_];

// ---------------- helpers ---------------------------------------------------------------
__device__ __forceinline__ uint32_t smem_u32(const void* p) {
    uint32_t a;
    asm("{ .reg .u64 t; cvta.to.shared.u64 t, %1; cvt.u32.u64 %0, t; }" : "=r"(a) : "l"(p));
    return a;
}
__device__ __forceinline__ void cp16s(uint32_t dst, const void* src) {
    asm volatile("cp.async.cg.shared.global [%0], [%1], 16;\n" :: "r"(dst), "l"(src));
}
__device__ __forceinline__ void mma16(float* c, const uint32_t* a, const uint32_t* b) {
    asm volatile(
        "mma.sync.aligned.m16n8k16.row.col.f32.f16.f16.f32 "
        "{%0,%1,%2,%3}, {%4,%5,%6,%7}, {%8,%9}, {%0,%1,%2,%3};\n"
        : "+f"(c[0]), "+f"(c[1]), "+f"(c[2]), "+f"(c[3])
        : "r"(a[0]), "r"(a[1]), "r"(a[2]), "r"(a[3]), "r"(b[0]), "r"(b[1]));
}
__device__ __forceinline__ void ldmA(uint32_t* r, uint32_t addr) {
    asm volatile("ldmatrix.sync.aligned.m8n8.x4.shared.b16 {%0,%1,%2,%3}, [%4];"
        : "=r"(r[0]), "=r"(r[1]), "=r"(r[2]), "=r"(r[3]) : "r"(addr));
}
__device__ __forceinline__ void ldmBT(uint32_t* r, uint32_t addr) {
    asm volatile("ldmatrix.sync.aligned.m8n8.x4.trans.shared.b16 {%0,%1,%2,%3}, [%4];"
        : "=r"(r[0]), "=r"(r[1]), "=r"(r[2]), "=r"(r[3]) : "r"(addr));
}
__device__ __forceinline__ uint32_t packh2(float lo, float hi) {
    __half2 h = __floats2half2_rn(lo, hi);
    return *reinterpret_cast<uint32_t*>(&h);
}

// ---------------- fp32 -> fp16 conversion (lane-contiguous, grid-stride) ----------------
__global__ void f2h(const float4* __restrict__ in, uint2* __restrict__ out, int n4) {
    int i = blockIdx.x * blockDim.x + threadIdx.x;
    const int stride = gridDim.x * blockDim.x;
    for (; i < n4; i += stride) {
        float4 v = in[i];
        __half2 a = __floats2half2_rn(v.x, v.y);
        __half2 b = __floats2half2_rn(v.z, v.w);
        uint2 o;
        o.x = *reinterpret_cast<uint32_t*>(&a);
        o.y = *reinterpret_cast<uint32_t*>(&b);
        out[i] = o;
    }
}

// ---------------- router -----------------------------------------------------------------
__global__ __launch_bounds__(256) void router_kernel(
    const float* __restrict__ x, const float* __restrict__ gw,
    const float* __restrict__ bias, int* __restrict__ eid_out, float* __restrict__ tw_out)
{
    const int t = blockIdx.x;
    const float* xr = x + (size_t)t * H_;
    float acc[E_];
    #pragma unroll
    for (int e = 0; e < E_; ++e) acc[e] = 0.f;
    for (int h = threadIdx.x; h < H_; h += 256) {
        float xv = xr[h];
        #pragma unroll
        for (int e = 0; e < E_; ++e) acc[e] += xv * gw[e * H_ + h];
    }
    #pragma unroll
    for (int e = 0; e < E_; ++e)
        #pragma unroll
        for (int o = 16; o > 0; o >>= 1)
            acc[e] += __shfl_down_sync(0xffffffffu, acc[e], o);

    __shared__ float red[8][E_];
    const int warp = threadIdx.x >> 5, lane = threadIdx.x & 31;
    if (lane == 0)
        for (int e = 0; e < E_; ++e) red[warp][e] = acc[e];
    __syncthreads();

    if (threadIdx.x == 0) {
        float sc[E_], sb[E_];
        for (int e = 0; e < E_; ++e) {
            float l = 0.f;
            for (int w = 0; w < 8; ++w) l += red[w][e];
            sc[e] = 1.f / (1.f + expf(-l));
            sb[e] = sc[e] + bias[e];
        }
        float gsc[4];
        for (int g = 0; g < 4; ++g) {
            float m1 = -1e30f, m2 = -1e30f;
            for (int j = 0; j < 4; ++j) {
                float v = sb[4*g + j];
                if (v > m1) { m2 = m1; m1 = v; } else if (v > m2) m2 = v;
            }
            gsc[g] = m1 + m2;
        }
        int gs0 = 0; float best = -1e30f;
        for (int g = 0; g < 4; ++g) if (gsc[g] > best) { best = gsc[g]; gs0 = g; }
        int gs1 = 0; best = -1e30f;
        for (int g = 0; g < 4; ++g) if (g != gs0 && gsc[g] > best) { best = gsc[g]; gs1 = g; }
        bool allow[E_];
        for (int e = 0; e < E_; ++e) { int g = e >> 2; allow[e] = (g == gs0 || g == gs1); }
        int ids[TK]; float ws[TK]; float wsum = 0.f;
        for (int k = 0; k < TK; ++k) {
            int be = 0; float bv = -1e30f;
            for (int e = 0; e < E_; ++e)
                if (allow[e] && sb[e] > bv) { bv = sb[e]; be = e; }
            allow[be] = false;
            ids[k] = be; ws[k] = sc[be]; wsum += sc[be];
        }
        const float inv = 1.f / wsum;
        for (int k = 0; k < TK; ++k) {
            eid_out[t*TK + k] = ids[k];
            tw_out [t*TK + k] = ws[k] * inv;
        }
    }
}

__global__ void build_lists(const int* __restrict__ ids, int* __restrict__ cnt,
                            int* __restrict__ rows) {
    int i = blockIdx.x * blockDim.x + threadIdx.x;
    if (i >= NA) return;
    int e = ids[i];
    int p = atomicAdd(&cnt[e], 1);
    rows[e * T_ + p] = i;
}

// ================= routed GEMM: fp16 A (smem), fp32 B streamed via regs ===================
// CTA 512 thr (16 warps, 4Mx4N), tile 256(M)x128(N), K-tile 32.
// A: cp.async fp16, 256 rows x 128B padded (4 chunks used, chunk c at c^(m&7)).
// B: LDG.128 fp32 (2/thread) -> cvt -> 1 STS.128 fp16, rows k 256B, chunk cn at cn^(k&7).
// N cols [0,64) from hcol0, [64,128) from hcol1 = halfBase + bx*colStep.
// rowmap: 1 gather tokens (A=rows[lr]>>2, C=rows[lr]) | 2 gather assignments.
// mode: 0 plain fp32 store *scale | 1 silu(g)*u*tw -> half C
#define SMEM2 135168   // epilogue staging 256*132*4; mainloop uses 81920

__global__ __launch_bounds__(512, 1)
void hgemm_w32(const __half* __restrict__ A, int lda,
               const float* __restrict__ Bf, int ldb, long long strideBe,
               void* __restrict__ Cv, int ldc,
               const int* __restrict__ rows_base, const int* __restrict__ cnt,
               const float* __restrict__ tw,
               int rowmap, int K, int colStep, int halfBase, int mode, float scale)
{
    extern __shared__ char smem[];
    const uint32_t sb = smem_u32(smem);
    const int e  = blockIdx.z;
    const int M  = cnt[e];
    const int m0 = blockIdx.y * 256;
    if (M <= 0 || m0 >= M) return;
    const int hcol0 = blockIdx.x * colStep;
    const int hcol1 = halfBase + blockIdx.x * colStep;
    const int* rows = rows_base + e * T_;
    const float* Be = Bf + (long long)e * strideBe;

    const int tid = threadIdx.x, warp = tid >> 5, lane = tid & 31;
    const int wm = (warp & 3) << 6, wn = (warp >> 2) << 5;
    const int lane15 = lane & 15, hi = lane >> 4;
    const int gid = lane >> 2, t4 = lane & 3;

    // A cp.async slots: 1024 chunks (256 rows x 4), 2 per thread
    int srcA[2]; uint32_t dA[2];
    #pragma unroll
    for (int p = 0; p < 2; ++p) {
        int idx = tid + p * 512;
        int m = idx >> 2, c = idx & 3;
        int lr = m0 + m; if (lr >= M) lr = M - 1;
        int a = rows[lr];
        int ar = (rowmap == 1) ? (a >> 2) : a;
        srcA[p] = ar * lda + (c << 3);
        dA[p]   = (uint32_t)(m * 128 + ((c ^ (m & 7)) << 4));
    }
    // B streaming slot: one 16-half chunk per thread per k-tile
    const int kB = tid >> 4, segB = tid & 15;
    const int c128 = segB << 3;
    const int gcolB = (c128 < 64) ? (hcol0 + c128) : (hcol1 + c128 - 64);
    const float* bSrc = Be + (long long)kB * ldb + gcolB;
    const uint32_t bDst = (uint32_t)(kB * 256 + ((segB ^ (kB & 7)) << 4));

    // ldmatrix addressing
    uint32_t amul[4]; int axor[4];
    #pragma unroll
    for (int mi = 0; mi < 4; ++mi) {
        int m = wm + mi * 16 + lane15;
        amul[mi] = (uint32_t)(m * 128);
        axor[mi] = m & 7;
    }
    uint32_t bLane[2];
    #pragma unroll
    for (int nj = 0; nj < 2; ++nj) {
        int basecn = (wn >> 3) + nj * 2;
        bLane[nj] = (uint32_t)(lane15 * 256 + (((basecn + hi) ^ (lane & 7)) << 4));
    }

    const uint32_t A0 = sb;            // 2 stages x 32768
    const uint32_t BH0 = sb + 65536;   // 2 stages x 8192

    float acc[4][4][4];
    #pragma unroll
    for (int mi = 0; mi < 4; ++mi)
        #pragma unroll
        for (int ni = 0; ni < 4; ++ni)
            #pragma unroll
            for (int q = 0; q < 4; ++q) acc[mi][ni][q] = 0.f;

    const int ktiles = K >> 5;

    auto issueA = [&](int kt) {
        const uint32_t aS = A0 + (uint32_t)((kt & 1) << 15);
        const __half* Ak = A + (kt << 5);
        cp16s(aS + dA[0], Ak + srcA[0]);
        cp16s(aS + dA[1], Ak + srcA[1]);
        asm volatile("cp.async.commit_group;\n");
    };

    float4 b0 = *(const float4*)bSrc;
    float4 b1 = *(const float4*)(bSrc + 4);
    issueA(0);

    for (int kt = 0; kt < ktiles; ++kt) {
        const int s = kt & 1;
        if (kt + 1 < ktiles) {
            issueA(kt + 1);
            asm volatile("cp.async.wait_group 1;\n");
        } else {
            asm volatile("cp.async.wait_group 0;\n");
        }
        // STS B(kt) fp16
        {
            uint4 hv;
            hv.x = packh2(b0.x, b0.y); hv.y = packh2(b0.z, b0.w);
            hv.z = packh2(b1.x, b1.y); hv.w = packh2(b1.z, b1.w);
            *(uint4*)(smem + 65536 + (s << 13) + bDst) = hv;
        }
        __syncthreads();
        if (kt + 1 < ktiles) {
            const float* src = bSrc + (long long)((kt + 1) << 5) * ldb;
            b0 = *(const float4*)src;
            b1 = *(const float4*)(src + 4);
        }
        const uint32_t aS = A0 + (uint32_t)(s << 15);
        const uint32_t bS = BH0 + (uint32_t)(s << 13);
        #pragma unroll
        for (int ks = 0; ks < 2; ++ks) {
            uint32_t af[4][4];
            #pragma unroll
            for (int mi = 0; mi < 4; ++mi)
                ldmA(af[mi], aS + amul[mi] +
                     (uint32_t)(((((ks << 1) | hi)) ^ axor[mi]) << 4));
            uint32_t bf0[4], bf1[4];
            ldmBT(bf0, bS + bLane[0] + (ks << 12));
            ldmBT(bf1, bS + bLane[1] + (ks << 12));
            #pragma unroll
            for (int mi = 0; mi < 4; ++mi) {
                mma16(acc[mi][0], af[mi], bf0 + 0);
                mma16(acc[mi][1], af[mi], bf0 + 2);
                mma16(acc[mi][2], af[mi], bf1 + 0);
                mma16(acc[mi][3], af[mi], bf1 + 2);
            }
        }
        __syncthreads();
    }

    if (mode == 0) {
        float* C = (float*)Cv;
        #pragma unroll
        for (int mi = 0; mi < 4; ++mi) {
            const int lr0 = m0 + wm + (mi << 4) + gid;
            const int lr1 = lr0 + 8;
            const bool v0 = lr0 < M, v1 = lr1 < M;
            long long cr0 = 0, cr1 = 0;
            if (v0) cr0 = rows[lr0];
            if (v1) cr1 = rows[lr1];
            #pragma unroll
            for (int ni = 0; ni < 4; ++ni) {
                const int cc = wn + (ni << 3) + (t4 << 1);
                const int gcol = (cc < 64) ? (hcol0 + cc) : (hcol1 + cc - 64);
                if (v0) { float2 v; v.x = acc[mi][ni][0]*scale; v.y = acc[mi][ni][1]*scale;
                          *(float2*)(C + cr0 * (long long)ldc + gcol) = v; }
                if (v1) { float2 v; v.x = acc[mi][ni][2]*scale; v.y = acc[mi][ni][3]*scale;
                          *(float2*)(C + cr1 * (long long)ldc + gcol) = v; }
            }
        }
    } else {
        // fused silu(gate)*up*tw epilogue via smem staging (256 rows, stride 132)
        float* stg = (float*)smem;
        #pragma unroll
        for (int mi = 0; mi < 4; ++mi) {
            const int r1 = wm + (mi << 4) + gid, r2 = r1 + 8;
            #pragma unroll
            for (int ni = 0; ni < 4; ++ni) {
                const int cc = wn + (ni << 3) + (t4 << 1);
                float2 v0; v0.x = acc[mi][ni][0]; v0.y = acc[mi][ni][1];
                float2 v1; v1.x = acc[mi][ni][2]; v1.y = acc[mi][ni][3];
                *(float2*)&stg[r1*132 + cc] = v0;
                *(float2*)&stg[r2*132 + cc] = v1;
            }
        }
        __syncthreads();
        const int r  = tid >> 1;
        const int ch = (tid & 1) << 5;
        const int lr = m0 + r;
        if (lr < M) {
            long long crow = rows[lr];
            const float f = tw[crow];
            const float* gp = stg + r*132 + ch;
            const float* up = gp + 64;
            __half* dst = (__half*)Cv + crow * (long long)ldc + hcol0 + ch;
            #pragma unroll
            for (int q = 0; q < 4; ++q) {
                float4 g0 = *(const float4*)(gp + (q << 3));
                float4 g1 = *(const float4*)(gp + (q << 3) + 4);
                float4 u0 = *(const float4*)(up + (q << 3));
                float4 u1 = *(const float4*)(up + (q << 3) + 4);
                float o0 = g0.x / (1.f + expf(-g0.x)) * u0.x * f;
                float o1 = g0.y / (1.f + expf(-g0.y)) * u0.y * f;
                float o2 = g0.z / (1.f + expf(-g0.z)) * u0.z * f;
                float o3 = g0.w / (1.f + expf(-g0.w)) * u0.w * f;
                float o4 = g1.x / (1.f + expf(-g1.x)) * u1.x * f;
                float o5 = g1.y / (1.f + expf(-g1.y)) * u1.y * f;
                float o6 = g1.z / (1.f + expf(-g1.z)) * u1.z * f;
                float o7 = g1.w / (1.f + expf(-g1.w)) * u1.w * f;
                uint4 o;
                o.x = packh2(o0, o1); o.y = packh2(o2, o3);
                o.z = packh2(o4, o5); o.w = packh2(o6, o7);
                *(uint4*)(dst + (q << 3)) = o;
            }
        }
    }
}

// ================= shared-expert GEMM: fp16 ldmatrix (unchanged from R7) =================
#define SMEM_BYTES 67584

__global__ __launch_bounds__(256, 2)
void hgemm(const __half* __restrict__ A, int lda,
           const __half* __restrict__ B, int ldb,
           void* __restrict__ Cv, int ldc,
           int Mdirect, int K, int colStep, int halfBase,
           int mode, float scale)
{
    extern __shared__ char smem[];
    const uint32_t sb = smem_u32(smem);
    const int M  = Mdirect;
    const int m0 = blockIdx.y * 128;
    const int hcol0 = blockIdx.x * colStep;
    const int hcol1 = halfBase + blockIdx.x * colStep;

    const int tid = threadIdx.x, warp = tid >> 5, lane = tid & 31;
    const int wm = (warp & 1) << 6, wn = (warp >> 1) << 5;
    const int lane15 = lane & 15, hi = lane >> 4;
    const int gid = lane >> 2, t4 = lane & 3;

    int srcA[4]; uint32_t dA[4];
    #pragma unroll
    for (int p = 0; p < 4; ++p) {
        int idx = tid + p * 256;
        int m = idx >> 3, c = idx & 7;
        int lr = m0 + m; if (lr >= M) lr = M - 1;
        srcA[p] = lr * lda + (c << 3);
        dA[p]   = (uint32_t)(m * 128 + ((c ^ (m & 7)) << 4));
    }
    int srcB[4]; uint32_t dB[4];
    #pragma unroll
    for (int p = 0; p < 4; ++p) {
        int idx = tid + p * 256;
        int k = idx >> 4, cn = idx & 15;
        int c128 = cn << 3;
        int gcol = (c128 < 64) ? (hcol0 + c128) : (hcol1 + c128 - 64);
        srcB[p] = k * ldb + gcol;
        dB[p]   = (uint32_t)(k * 256 + ((cn ^ (k & 7)) << 4));
    }

    uint32_t amul[4]; int axor[4];
    #pragma unroll
    for (int mi = 0; mi < 4; ++mi) {
        int m = wm + mi * 16 + lane15;
        amul[mi] = (uint32_t)(m * 128);
        axor[mi] = m & 7;
    }
    uint32_t bLane[2];
    #pragma unroll
    for (int nj = 0; nj < 2; ++nj) {
        int basecn = (wn >> 3) + nj * 2;
        bLane[nj] = (uint32_t)(lane15 * 256 + (((basecn + hi) ^ (lane & 7)) << 4));
    }

    float acc[4][4][4];
    #pragma unroll
    for (int mi = 0; mi < 4; ++mi)
        #pragma unroll
        for (int ni = 0; ni < 4; ++ni)
            #pragma unroll
            for (int q = 0; q < 4; ++q) acc[mi][ni][q] = 0.f;

    const int ktiles = K >> 6;

    auto issue = [&](int kt, int stage) {
        const int k0 = kt << 6;
        const __half* Ak = A + k0;
        const __half* Bk = B + (long long)k0 * ldb;
        const uint32_t aS = sb + stage * 32768;
        const uint32_t bS = aS + 16384;
        #pragma unroll
        for (int p = 0; p < 4; ++p) cp16s(aS + dA[p], Ak + srcA[p]);
        #pragma unroll
        for (int p = 0; p < 4; ++p) cp16s(bS + dB[p], Bk + srcB[p]);
        asm volatile("cp.async.commit_group;\n");
    };

    issue(0, 0);
    for (int kt = 0; kt < ktiles; ++kt) {
        const int stage = kt & 1;
        if (kt + 1 < ktiles) {
            issue(kt + 1, stage ^ 1);
            asm volatile("cp.async.wait_group 1;\n");
        } else {
            asm volatile("cp.async.wait_group 0;\n");
        }
        __syncthreads();
        const uint32_t aS = sb + stage * 32768;
        const uint32_t bS = aS + 16384;
        #pragma unroll
        for (int ks = 0; ks < 4; ++ks) {
            uint32_t af[4][4];
            #pragma unroll
            for (int mi = 0; mi < 4; ++mi)
                ldmA(af[mi], aS + amul[mi] +
                     (uint32_t)(((((ks << 1) | hi)) ^ axor[mi]) << 4));
            uint32_t bf0[4], bf1[4];
            ldmBT(bf0, bS + bLane[0] + (ks << 12));
            ldmBT(bf1, bS + bLane[1] + (ks << 12));
            #pragma unroll
            for (int mi = 0; mi < 4; ++mi) {
                mma16(acc[mi][0], af[mi], bf0 + 0);
                mma16(acc[mi][1], af[mi], bf0 + 2);
                mma16(acc[mi][2], af[mi], bf1 + 0);
                mma16(acc[mi][3], af[mi], bf1 + 2);
            }
        }
        __syncthreads();
    }

    if (mode == 0) {
        float* C = (float*)Cv;
        #pragma unroll
        for (int mi = 0; mi < 4; ++mi) {
            const int lr0 = m0 + wm + (mi << 4) + gid;
            const int lr1 = lr0 + 8;
            #pragma unroll
            for (int ni = 0; ni < 4; ++ni) {
                const int cc = wn + (ni << 3) + (t4 << 1);
                const int gcol = (cc < 64) ? (hcol0 + cc) : (hcol1 + cc - 64);
                { float2 v; v.x = acc[mi][ni][0]*scale; v.y = acc[mi][ni][1]*scale;
                  *(float2*)(C + (long long)lr0 * ldc + gcol) = v; }
                { float2 v; v.x = acc[mi][ni][2]*scale; v.y = acc[mi][ni][3]*scale;
                  *(float2*)(C + (long long)lr1 * ldc + gcol) = v; }
            }
        }
    } else {
        float* stg = (float*)smem;
        #pragma unroll
        for (int mi = 0; mi < 4; ++mi) {
            const int r1 = wm + (mi << 4) + gid, r2 = r1 + 8;
            #pragma unroll
            for (int ni = 0; ni < 4; ++ni) {
                const int cc = wn + (ni << 3) + (t4 << 1);
                float2 v0; v0.x = acc[mi][ni][0]; v0.y = acc[mi][ni][1];
                float2 v1; v1.x = acc[mi][ni][2]; v1.y = acc[mi][ni][3];
                *(float2*)&stg[r1*132 + cc] = v0;
                *(float2*)&stg[r2*132 + cc] = v1;
            }
        }
        __syncthreads();
        const int r  = tid >> 1;
        const int ch = (tid & 1) << 5;
        const int lr = m0 + r;
        {
            const float* gp = stg + r*132 + ch;
            const float* up = gp + 64;
            __half* dst = (__half*)Cv + (long long)lr * ldc + hcol0 + ch;
            #pragma unroll
            for (int q = 0; q < 4; ++q) {
                float4 g0 = *(const float4*)(gp + (q << 3));
                float4 g1 = *(const float4*)(gp + (q << 3) + 4);
                float4 u0 = *(const float4*)(up + (q << 3));
                float4 u1 = *(const float4*)(up + (q << 3) + 4);
                float o0 = g0.x / (1.f + expf(-g0.x)) * u0.x;
                float o1 = g0.y / (1.f + expf(-g0.y)) * u0.y;
                float o2 = g0.z / (1.f + expf(-g0.z)) * u0.z;
                float o3 = g0.w / (1.f + expf(-g0.w)) * u0.w;
                float o4 = g1.x / (1.f + expf(-g1.x)) * u1.x;
                float o5 = g1.y / (1.f + expf(-g1.y)) * u1.y;
                float o6 = g1.z / (1.f + expf(-g1.z)) * u1.z;
                float o7 = g1.w / (1.f + expf(-g1.w)) * u1.w;
                uint4 o;
                o.x = packh2(o0, o1); o.y = packh2(o2, o3);
                o.z = packh2(o4, o5); o.w = packh2(o6, o7);
                *(uint4*)(dst + (q << 3)) = o;
            }
        }
    }
}

// ---------------- combine (vectorized) -----------------------------------------------------
__global__ void combine_k(const float4* __restrict__ routed, const float4* __restrict__ sh,
                          float4* __restrict__ out) {
    int idx = blockIdx.x * blockDim.x + threadIdx.x;          // over T*H/4
    if (idx >= T_ * H_ / 4) return;
    const int t = idx >> 9;                                    // H/4 = 512
    const size_t b = ((size_t)t * TK) * 512 + (idx & 511);
    float4 a0 = routed[b], a1 = routed[b + 512], a2 = routed[b + 1024], a3 = routed[b + 1536];
    float4 s = sh[idx];
    float4 o;
    o.x = a0.x + a1.x + a2.x + a3.x + s.x;
    o.y = a0.y + a1.y + a2.y + a3.y + s.y;
    o.z = a0.z + a1.z + a2.z + a3.z + s.z;
    o.w = a0.w + a1.w + a2.w + a3.w + s.w;
    out[idx] = o;
}

// ---------------- entry ---------------------------------------------------------------------
extern "C" void kernel_launch(void* const* d_in, const int* in_sizes, int n_in,
                              void* d_out, int out_size) {
    const float* x    = (const float*)d_in[0];  // [1024, 2048]
    const float* gw   = (const float*)d_in[1];  // [16, 2048]
    const float* bias = (const float*)d_in[2];  // [16]
    const float* w_gu = (const float*)d_in[3];  // [16, 2048, 2816] fp32 (consumed directly)
    const float* w_dn = (const float*)d_in[4];  // [16, 1408, 2048] fp32 (consumed directly)
    const float* s_gu = (const float*)d_in[5];  // [2048, 5632]
    const float* s_dn = (const float*)d_in[6];  // [2816, 2048]
    float* out = (float*)d_out;                 // [1024, 2048] fp32

    __half *pXH, *pSGUH, *pSDNH, *pACTH, *pSACTH;
    float *pROUT, *pSH, *pTW;
    int *pEID, *pCNT, *pROWS;
    cudaGetSymbolAddress((void**)&pXH,    g_XH);
    cudaGetSymbolAddress((void**)&pSGUH,  g_SGUH);
    cudaGetSymbolAddress((void**)&pSDNH,  g_SDNH);
    cudaGetSymbolAddress((void**)&pACTH,  g_ACTH);
    cudaGetSymbolAddress((void**)&pSACTH, g_SACTH);
    cudaGetSymbolAddress((void**)&pROUT,  g_ROUT);
    cudaGetSymbolAddress((void**)&pSH,    g_SH);
    cudaGetSymbolAddress((void**)&pEID,   g_eid);
    cudaGetSymbolAddress((void**)&pTW,    g_tw);
    cudaGetSymbolAddress((void**)&pCNT,   g_cnt);
    cudaGetSymbolAddress((void**)&pROWS,  g_rows);

    cudaFuncSetAttribute(hgemm, cudaFuncAttributeMaxDynamicSharedMemorySize, SMEM_BYTES);
    cudaFuncSetAttribute(hgemm_w32, cudaFuncAttributeMaxDynamicSharedMemorySize, SMEM2);

    // 0. fp32 -> fp16 (only x + shared weights; routed weights consumed as fp32 in-GEMM)
    f2h<<<1184, 256>>>((const float4*)x,    (uint2*)pXH,    T_*H_/4);
    f2h<<<1184, 256>>>((const float4*)s_gu, (uint2*)pSGUH,  H_*2*IS_/4);
    f2h<<<1184, 256>>>((const float4*)s_dn, (uint2*)pSDNH,  IS_*H_/4);

    // 1. router
    router_kernel<<<T_, 256>>>(x, gw, bias, pEID, pTW);
    // 2. per-expert assignment lists
    cudaMemsetAsync(pCNT, 0, E_ * sizeof(int));
    build_lists<<<NA / 256, 256>>>(pEID, pCNT, pROWS);
    // 3. routed gate_up fused (fp32 weights streamed): silu*up*tw -> ACTH
    {
        dim3 g(I_ / 64, T_ / 256, E_);
        hgemm_w32<<<g, 512, SMEM2>>>(pXH, H_, w_gu, 2*I_, (long long)H_ * (2*I_),
                                     pACTH, I_, pROWS, pCNT, pTW,
                                     /*rowmap*/1, /*K*/H_, /*colStep*/64, /*halfBase*/I_,
                                     /*mode*/1, 1.0f);
    }
    // 4. routed down * 2.5 -> ROUT slots (fp32 weights streamed)
    {
        dim3 g(H_ / 128, T_ / 256, E_);
        hgemm_w32<<<g, 512, SMEM2>>>(pACTH, I_, w_dn, H_, (long long)I_ * H_,
                                     pROUT, H_, pROWS, pCNT, pTW,
                                     /*rowmap*/2, /*K*/I_, /*colStep*/128, /*halfBase*/64,
                                     /*mode*/0, 2.5f);
    }
    // 5. shared gate_up fused -> SACTH
    {
        dim3 g(IS_ / 64, T_ / 128, 1);
        hgemm<<<g, 256, SMEM_BYTES>>>(pXH, H_, pSGUH, 2*IS_,
                                      pSACTH, IS_, T_, H_, 64, IS_, 2, 1.0f);
    }
    // 6. shared down -> SH
    {
        dim3 g(H_ / 128, T_ / 128, 1);
        hgemm<<<g, 256, SMEM_BYTES>>>(pSACTH, IS_, pSDNH, H_,
                                      pSH, H_, T_, IS_, 128, 64, 0, 1.0f);
    }
    // 7. out = sum_k routed[t,k,:] + shared[t,:]
    combine_k<<<(T_ * H_ / 4 + 255) / 256, 256>>>((const float4*)pROUT, (const float4*)pSH,
                                                  (float4*)out);
}

// round 11
// speedup vs baseline: 1.1383x; 1.1383x over previous
#include <cuda_runtime.h>
#include <cuda_fp16.h>
#include <cstdint>
#include <math.h>

#define T_  1024
#define H_  2048
#define I_  1408
#define E_  16
#define IS_ 2816
#define TK  4
#define NA  (T_*TK)   // 4096 token-expert assignments

// ---------------- scratch (device globals) ----------------------------------------------
__device__ __half g_XH   [(size_t)T_ * H_];
__device__ __half g_WGUH [(size_t)E_ * H_ * (2*I_)];
__device__ __half g_WDNH [(size_t)E_ * I_ * H_];
__device__ __half g_SGUH [(size_t)H_ * (2*IS_)];
__device__ __half g_SDNH [(size_t)IS_ * H_];
__device__ __half g_ACTH [(size_t)NA * I_];
__device__ __half g_SACTH[(size_t)T_ * IS_];
__device__ float  g_ROUT [(size_t)NA * H_];
__device__ float  g_SH   [(size_t)T_ * H_];
__device__ int    g_eid [NA];
__device__ float  g_tw  [NA];
__device__ int    g_cnt [E_];
__device__ int    g_rows[E_ * T_];

// ---------------- helpers ---------------------------------------------------------------
__device__ __forceinline__ uint32_t smem_u32(const void* p) {
    uint32_t a;
    asm("{ .reg .u64 t; cvta.to.shared.u64 t, %1; cvt.u32.u64 %0, t; }" : "=r"(a) : "l"(p));
    return a;
}
__device__ __forceinline__ void cp16s(uint32_t dst, const void* src) {
    asm volatile("cp.async.cg.shared.global [%0], [%1], 16;\n" :: "r"(dst), "l"(src));
}
__device__ __forceinline__ void mma16(float* c, const uint32_t* a, const uint32_t* b) {
    asm volatile(
        "mma.sync.aligned.m16n8k16.row.col.f32.f16.f16.f32 "
        "{%0,%1,%2,%3}, {%4,%5,%6,%7}, {%8,%9}, {%0,%1,%2,%3};\n"
        : "+f"(c[0]), "+f"(c[1]), "+f"(c[2]), "+f"(c[3])
        : "r"(a[0]), "r"(a[1]), "r"(a[2]), "r"(a[3]), "r"(b[0]), "r"(b[1]));
}
__device__ __forceinline__ void ldmA(uint32_t* r, uint32_t addr) {
    asm volatile("ldmatrix.sync.aligned.m8n8.x4.shared.b16 {%0,%1,%2,%3}, [%4];"
        : "=r"(r[0]), "=r"(r[1]), "=r"(r[2]), "=r"(r[3]) : "r"(addr));
}
__device__ __forceinline__ void ldmBT(uint32_t* r, uint32_t addr) {
    asm volatile("ldmatrix.sync.aligned.m8n8.x4.trans.shared.b16 {%0,%1,%2,%3}, [%4];"
        : "=r"(r[0]), "=r"(r[1]), "=r"(r[2]), "=r"(r[3]) : "r"(addr));
}
__device__ __forceinline__ uint32_t packh2(float lo, float hi) {
    __half2 h = __floats2half2_rn(lo, hi);
    return *reinterpret_cast<uint32_t*>(&h);
}

// ---------------- fp32 -> fp16 conversion (lane-contiguous, grid-stride) ----------------
__global__ void f2h(const float4* __restrict__ in, uint2* __restrict__ out, int n4) {
    int i = blockIdx.x * blockDim.x + threadIdx.x;
    const int stride = gridDim.x * blockDim.x;
    for (; i < n4; i += stride) {
        float4 v = in[i];
        __half2 a = __floats2half2_rn(v.x, v.y);
        __half2 b = __floats2half2_rn(v.z, v.w);
        uint2 o;
        o.x = *reinterpret_cast<uint32_t*>(&a);
        o.y = *reinterpret_cast<uint32_t*>(&b);
        out[i] = o;
    }
}

// ---------------- router -----------------------------------------------------------------
__global__ __launch_bounds__(256) void router_kernel(
    const float* __restrict__ x, const float* __restrict__ gw,
    const float* __restrict__ bias, int* __restrict__ eid_out, float* __restrict__ tw_out)
{
    const int t = blockIdx.x;
    const float* xr = x + (size_t)t * H_;
    float acc[E_];
    #pragma unroll
    for (int e = 0; e < E_; ++e) acc[e] = 0.f;
    for (int h = threadIdx.x; h < H_; h += 256) {
        float xv = xr[h];
        #pragma unroll
        for (int e = 0; e < E_; ++e) acc[e] += xv * gw[e * H_ + h];
    }
    #pragma unroll
    for (int e = 0; e < E_; ++e)
        #pragma unroll
        for (int o = 16; o > 0; o >>= 1)
            acc[e] += __shfl_down_sync(0xffffffffu, acc[e], o);

    __shared__ float red[8][E_];
    const int warp = threadIdx.x >> 5, lane = threadIdx.x & 31;
    if (lane == 0)
        for (int e = 0; e < E_; ++e) red[warp][e] = acc[e];
    __syncthreads();

    if (threadIdx.x == 0) {
        float sc[E_], sb[E_];
        for (int e = 0; e < E_; ++e) {
            float l = 0.f;
            for (int w = 0; w < 8; ++w) l += red[w][e];
            sc[e] = 1.f / (1.f + expf(-l));
            sb[e] = sc[e] + bias[e];
        }
        float gsc[4];
        for (int g = 0; g < 4; ++g) {
            float m1 = -1e30f, m2 = -1e30f;
            for (int j = 0; j < 4; ++j) {
                float v = sb[4*g + j];
                if (v > m1) { m2 = m1; m1 = v; } else if (v > m2) m2 = v;
            }
            gsc[g] = m1 + m2;
        }
        int gs0 = 0; float best = -1e30f;
        for (int g = 0; g < 4; ++g) if (gsc[g] > best) { best = gsc[g]; gs0 = g; }
        int gs1 = 0; best = -1e30f;
        for (int g = 0; g < 4; ++g) if (g != gs0 && gsc[g] > best) { best = gsc[g]; gs1 = g; }
        bool allow[E_];
        for (int e = 0; e < E_; ++e) { int g = e >> 2; allow[e] = (g == gs0 || g == gs1); }
        int ids[TK]; float ws[TK]; float wsum = 0.f;
        for (int k = 0; k < TK; ++k) {
            int be = 0; float bv = -1e30f;
            for (int e = 0; e < E_; ++e)
                if (allow[e] && sb[e] > bv) { bv = sb[e]; be = e; }
            allow[be] = false;
            ids[k] = be; ws[k] = sc[be]; wsum += sc[be];
        }
        const float inv = 1.f / wsum;
        for (int k = 0; k < TK; ++k) {
            eid_out[t*TK + k] = ids[k];
            tw_out [t*TK + k] = ws[k] * inv;
        }
    }
}

__global__ void build_lists(const int* __restrict__ ids, int* __restrict__ cnt,
                            int* __restrict__ rows) {
    int i = blockIdx.x * blockDim.x + threadIdx.x;
    if (i >= NA) return;
    int e = ids[i];
    int p = atomicAdd(&cnt[e], 1);
    rows[e * T_ + p] = i;
}

// ---------------- fp16 ldmatrix HGEMM (R7 proven path) -------------------------------------
// CTA 256 thr (8 warps, 2(M)x4(N)), tile 128x128, K-tile 64, fp16 smem double-buffered.
// rowmap: 0 direct | 1 gather tokens (A=rows[lr]>>2, C=rows[lr]) | 2 gather assignments.
// mode: 0 plain fp32 store *scale | 1 silu(g)*u*tw -> half C | 2 silu(g)*u -> half C
#define SMEM_BYTES 67584   // max(2*32768 stages, 128*132*4 staging)

__global__ __launch_bounds__(256, 2)
void hgemm(const __half* __restrict__ A, int lda,
           const __half* __restrict__ B, int ldb, long long strideBe,
           void* __restrict__ Cv, int ldc,
           const int* __restrict__ rows_base, const int* __restrict__ cnt,
           const float* __restrict__ tw,
           int rowmap, int Mdirect, int K, int colStep, int halfBase,
           int mode, float scale)
{
    extern __shared__ char smem[];
    const uint32_t sb = smem_u32(smem);
    const int e  = blockIdx.z;
    const int M  = rowmap ? cnt[e] : Mdirect;
    const int m0 = blockIdx.y * 128;
    if (M <= 0 || m0 >= M) return;
    const int hcol0 = blockIdx.x * colStep;
    const int hcol1 = halfBase + blockIdx.x * colStep;
    const int* rows = rows_base + e * T_;
    const __half* Be = B + (long long)e * strideBe;

    const int tid = threadIdx.x, warp = tid >> 5, lane = tid & 31;
    const int wm = (warp & 1) << 6, wn = (warp >> 1) << 5;
    const int lane15 = lane & 15, hi = lane >> 4;
    const int gid = lane >> 2, t4 = lane & 3;

    int srcA[4]; uint32_t dA[4];
    #pragma unroll
    for (int p = 0; p < 4; ++p) {
        int idx = tid + p * 256;
        int m = idx >> 3, c = idx & 7;
        int lr = m0 + m; if (lr >= M) lr = M - 1;
        int ar;
        if (rowmap == 0)      ar = lr;
        else { int a = rows[lr]; ar = (rowmap == 1) ? (a >> 2) : a; }
        srcA[p] = ar * lda + (c << 3);
        dA[p]   = (uint32_t)(m * 128 + ((c ^ (m & 7)) << 4));
    }
    int srcB[4]; uint32_t dB[4];
    #pragma unroll
    for (int p = 0; p < 4; ++p) {
        int idx = tid + p * 256;
        int k = idx >> 4, cn = idx & 15;
        int c128 = cn << 3;
        int gcol = (c128 < 64) ? (hcol0 + c128) : (hcol1 + c128 - 64);
        srcB[p] = k * ldb + gcol;
        dB[p]   = (uint32_t)(k * 256 + ((cn ^ (k & 7)) << 4));
    }

    uint32_t amul[4]; int axor[4];
    #pragma unroll
    for (int mi = 0; mi < 4; ++mi) {
        int m = wm + mi * 16 + lane15;
        amul[mi] = (uint32_t)(m * 128);
        axor[mi] = m & 7;
    }
    uint32_t bLane[2];
    #pragma unroll
    for (int nj = 0; nj < 2; ++nj) {
        int basecn = (wn >> 3) + nj * 2;
        bLane[nj] = (uint32_t)(lane15 * 256 + (((basecn + hi) ^ (lane & 7)) << 4));
    }

    float acc[4][4][4];
    #pragma unroll
    for (int mi = 0; mi < 4; ++mi)
        #pragma unroll
        for (int ni = 0; ni < 4; ++ni)
            #pragma unroll
            for (int q = 0; q < 4; ++q) acc[mi][ni][q] = 0.f;

    const int ktiles = K >> 6;

    auto issue = [&](int kt, int stage) {
        const int k0 = kt << 6;
        const __half* Ak = A + k0;
        const __half* Bk = Be + (long long)k0 * ldb;
        const uint32_t aS = sb + stage * 32768;
        const uint32_t bS = aS + 16384;
        #pragma unroll
        for (int p = 0; p < 4; ++p) cp16s(aS + dA[p], Ak + srcA[p]);
        #pragma unroll
        for (int p = 0; p < 4; ++p) cp16s(bS + dB[p], Bk + srcB[p]);
        asm volatile("cp.async.commit_group;\n");
    };

    issue(0, 0);
    for (int kt = 0; kt < ktiles; ++kt) {
        const int stage = kt & 1;
        if (kt + 1 < ktiles) {
            issue(kt + 1, stage ^ 1);
            asm volatile("cp.async.wait_group 1;\n");
        } else {
            asm volatile("cp.async.wait_group 0;\n");
        }
        __syncthreads();
        const uint32_t aS = sb + stage * 32768;
        const uint32_t bS = aS + 16384;
        #pragma unroll
        for (int ks = 0; ks < 4; ++ks) {
            uint32_t af[4][4];
            #pragma unroll
            for (int mi = 0; mi < 4; ++mi)
                ldmA(af[mi], aS + amul[mi] +
                     (uint32_t)(((((ks << 1) | hi)) ^ axor[mi]) << 4));
            uint32_t bf0[4], bf1[4];
            ldmBT(bf0, bS + bLane[0] + (ks << 12));
            ldmBT(bf1, bS + bLane[1] + (ks << 12));
            #pragma unroll
            for (int mi = 0; mi < 4; ++mi) {
                mma16(acc[mi][0], af[mi], bf0 + 0);
                mma16(acc[mi][1], af[mi], bf0 + 2);
                mma16(acc[mi][2], af[mi], bf1 + 0);
                mma16(acc[mi][3], af[mi], bf1 + 2);
            }
        }
        __syncthreads();
    }

    if (mode == 0) {
        float* C = (float*)Cv;
        #pragma unroll
        for (int mi = 0; mi < 4; ++mi) {
            const int lr0 = m0 + wm + (mi << 4) + gid;
            const int lr1 = lr0 + 8;
            const bool v0 = lr0 < M, v1 = lr1 < M;
            long long cr0 = 0, cr1 = 0;
            if (rowmap == 0) { cr0 = lr0; cr1 = lr1; }
            else { if (v0) cr0 = rows[lr0]; if (v1) cr1 = rows[lr1]; }
            #pragma unroll
            for (int ni = 0; ni < 4; ++ni) {
                const int cc = wn + (ni << 3) + (t4 << 1);
                const int gcol = (cc < 64) ? (hcol0 + cc) : (hcol1 + cc - 64);
                if (v0) { float2 v; v.x = acc[mi][ni][0]*scale; v.y = acc[mi][ni][1]*scale;
                          *(float2*)(C + cr0 * (long long)ldc + gcol) = v; }
                if (v1) { float2 v; v.x = acc[mi][ni][2]*scale; v.y = acc[mi][ni][3]*scale;
                          *(float2*)(C + cr1 * (long long)ldc + gcol) = v; }
            }
        }
    } else {
        // fused silu(gate)*up epilogue via smem staging (stride 132 floats)
        float* stg = (float*)smem;
        #pragma unroll
        for (int mi = 0; mi < 4; ++mi) {
            const int r1 = wm + (mi << 4) + gid, r2 = r1 + 8;
            #pragma unroll
            for (int ni = 0; ni < 4; ++ni) {
                const int cc = wn + (ni << 3) + (t4 << 1);
                float2 v0; v0.x = acc[mi][ni][0]; v0.y = acc[mi][ni][1];
                float2 v1; v1.x = acc[mi][ni][2]; v1.y = acc[mi][ni][3];
                *(float2*)&stg[r1*132 + cc] = v0;
                *(float2*)&stg[r2*132 + cc] = v1;
            }
        }
        __syncthreads();
        const int r  = tid >> 1;
        const int ch = (tid & 1) << 5;
        const int lr = m0 + r;
        if (lr < M) {
            long long crow = rowmap ? rows[lr] : lr;
            const float f = (mode == 1) ? tw[crow] : 1.f;
            const float* gp = stg + r*132 + ch;
            const float* up = gp + 64;
            __half* dst = (__half*)Cv + crow * (long long)ldc + hcol0 + ch;
            #pragma unroll
            for (int q = 0; q < 4; ++q) {
                float4 g0 = *(const float4*)(gp + (q << 3));
                float4 g1 = *(const float4*)(gp + (q << 3) + 4);
                float4 u0 = *(const float4*)(up + (q << 3));
                float4 u1 = *(const float4*)(up + (q << 3) + 4);
                float o0 = g0.x / (1.f + expf(-g0.x)) * u0.x * f;
                float o1 = g0.y / (1.f + expf(-g0.y)) * u0.y * f;
                float o2 = g0.z / (1.f + expf(-g0.z)) * u0.z * f;
                float o3 = g0.w / (1.f + expf(-g0.w)) * u0.w * f;
                float o4 = g1.x / (1.f + expf(-g1.x)) * u1.x * f;
                float o5 = g1.y / (1.f + expf(-g1.y)) * u1.y * f;
                float o6 = g1.z / (1.f + expf(-g1.z)) * u1.z * f;
                float o7 = g1.w / (1.f + expf(-g1.w)) * u1.w * f;
                uint4 o;
                o.x = packh2(o0, o1); o.y = packh2(o2, o3);
                o.z = packh2(o4, o5); o.w = packh2(o6, o7);
                *(uint4*)(dst + (q << 3)) = o;
            }
        }
    }
}

// ---------------- combine (vectorized) -----------------------------------------------------
__global__ void combine_k(const float4* __restrict__ routed, const float4* __restrict__ sh,
                          float4* __restrict__ out) {
    int idx = blockIdx.x * blockDim.x + threadIdx.x;          // over T*H/4
    if (idx >= T_ * H_ / 4) return;
    const int t = idx >> 9;                                    // H/4 = 512
    const size_t b = ((size_t)t * TK) * 512 + (idx & 511);
    float4 a0 = routed[b], a1 = routed[b + 512], a2 = routed[b + 1024], a3 = routed[b + 1536];
    float4 s = sh[idx];
    float4 o;
    o.x = a0.x + a1.x + a2.x + a3.x + s.x;
    o.y = a0.y + a1.y + a2.y + a3.y + s.y;
    o.z = a0.z + a1.z + a2.z + a3.z + s.z;
    o.w = a0.w + a1.w + a2.w + a3.w + s.w;
    out[idx] = o;
}

// ---------------- entry ---------------------------------------------------------------------
extern "C" void kernel_launch(void* const* d_in, const int* in_sizes, int n_in,
                              void* d_out, int out_size) {
    const float* x    = (const float*)d_in[0];  // [1024, 2048]
    const float* gw   = (const float*)d_in[1];  // [16, 2048]
    const float* bias = (const float*)d_in[2];  // [16]
    const float* w_gu = (const float*)d_in[3];  // [16, 2048, 2816]
    const float* w_dn = (const float*)d_in[4];  // [16, 1408, 2048]
    const float* s_gu = (const float*)d_in[5];  // [2048, 5632]
    const float* s_dn = (const float*)d_in[6];  // [2816, 2048]
    float* out = (float*)d_out;                 // [1024, 2048] fp32

    __half *pXH, *pWGUH, *pWDNH, *pSGUH, *pSDNH, *pACTH, *pSACTH;
    float *pROUT, *pSH, *pTW;
    int *pEID, *pCNT, *pROWS;
    cudaGetSymbolAddress((void**)&pXH,    g_XH);
    cudaGetSymbolAddress((void**)&pWGUH,  g_WGUH);
    cudaGetSymbolAddress((void**)&pWDNH,  g_WDNH);
    cudaGetSymbolAddress((void**)&pSGUH,  g_SGUH);
    cudaGetSymbolAddress((void**)&pSDNH,  g_SDNH);
    cudaGetSymbolAddress((void**)&pACTH,  g_ACTH);
    cudaGetSymbolAddress((void**)&pSACTH, g_SACTH);
    cudaGetSymbolAddress((void**)&pROUT,  g_ROUT);
    cudaGetSymbolAddress((void**)&pSH,    g_SH);
    cudaGetSymbolAddress((void**)&pEID,   g_eid);
    cudaGetSymbolAddress((void**)&pTW,    g_tw);
    cudaGetSymbolAddress((void**)&pCNT,   g_cnt);
    cudaGetSymbolAddress((void**)&pROWS,  g_rows);

    cudaFuncSetAttribute(hgemm, cudaFuncAttributeMaxDynamicSharedMemorySize, SMEM_BYTES);

    // 0. fp32 -> fp16 conversions (coalesced grid-stride)
    f2h<<<2368, 256>>>((const float4*)x,    (uint2*)pXH,    T_*H_/4);
    f2h<<<2368, 256>>>((const float4*)w_gu, (uint2*)pWGUH,  E_*H_*(2*I_)/4);
    f2h<<<2368, 256>>>((const float4*)w_dn, (uint2*)pWDNH,  E_*I_*H_/4);
    f2h<<<2368, 256>>>((const float4*)s_gu, (uint2*)pSGUH,  H_*(2*IS_)/4);
    f2h<<<2368, 256>>>((const float4*)s_dn, (uint2*)pSDNH,  IS_*H_/4);

    // 1. router
    router_kernel<<<T_, 256>>>(x, gw, bias, pEID, pTW);
    // 2. per-expert assignment lists
    cudaMemsetAsync(pCNT, 0, E_ * sizeof(int));
    build_lists<<<NA / 256, 256>>>(pEID, pCNT, pROWS);
    // 3. routed gate_up fused: 64 gate + 64 up cols -> silu*up*tw -> ACTH (half)
    {
        dim3 g(I_ / 64, T_ / 128, E_);
        hgemm<<<g, 256, SMEM_BYTES>>>(pXH, H_, pWGUH, 2*I_, (long long)H_ * (2*I_),
                                      pACTH, I_, pROWS, pCNT, pTW,
                                      1, 0, H_, 64, I_, 1, 1.0f);
    }
    // 4. routed down * 2.5 -> ROUT slots (fp32, deterministic scatter)
    {
        dim3 g(H_ / 128, T_ / 128, E_);
        hgemm<<<g, 256, SMEM_BYTES>>>(pACTH, I_, pWDNH, H_, (long long)I_ * H_,
                                      pROUT, H_, pROWS, pCNT, pTW,
                                      2, 0, I_, 128, 64, 0, 2.5f);
    }
    // 5. shared gate_up fused -> SACTH (half)
    {
        dim3 g(IS_ / 64, T_ / 128, 1);
        hgemm<<<g, 256, SMEM_BYTES>>>(pXH, H_, pSGUH, 2*IS_, 0,
                                      pSACTH, IS_, pROWS, pCNT, pTW,
                                      0, T_, H_, 64, IS_, 2, 1.0f);
    }
    // 6. shared down -> SH (fp32)
    {
        dim3 g(H_ / 128, T_ / 128, 1);
        hgemm<<<g, 256, SMEM_BYTES>>>(pSACTH, IS_, pSDNH, H_, 0,
                                      pSH, H_, pROWS, pCNT, pTW,
                                      0, T_, IS_, 128, 64, 0, 1.0f);
    }
    // 7. out = sum_k routed[t,k,:] + shared[t,:]
    combine_k<<<(T_ * H_ / 4 + 255) / 256, 256>>>((const float4*)pROUT, (const float4*)pSH,
                                                  (float4*)out);
}